// round 5
// baseline (speedup 1.0000x reference)
#include <cuda_runtime.h>
#include <cuda_fp16.h>
#include <cstdint>

#define ZDIM   128
#define MDIM   8192
#define NB     128
#define MT     64                    // M rows per CTA
#define NCTA   (MDIM / MT)           // 128 CTAs
#define KT     64                    // K per tile (fp16 tile row = 128B)
#define NITER  (MDIM / KT)           // 128
#define STAGES 8
#define AT_BYTES   (MT * 128)        // 8 KB fp16 B-tile
#define RING_BYTES (STAGES * AT_BYTES)        // 64 KB
#define FULL_OFF   RING_BYTES
#define EMPTY_OFF  (RING_BYTES + 64)
#define SS_OFF     (RING_BYTES + 128)
#define SMEM_DYN   (RING_BYTES + 1536)
#define OUT_PLANE  (NB * MDIM)

// eps packed into m16n8k16 B-fragment layout, fp16 (2 MB).
// uint4 index: (kc*8 + nP)*32 + lane ; kc = k/16 (0..511), nP = n/16 (0..7)
// lane's 4 u32 = {b0,b1 of n8-group 2nP} , {b0,b1 of group 2nP+1}
__device__ __align__(16) __half2 g_epsh[OUT_PLANE / 2];

static __device__ __forceinline__ uint32_t smem_u32(const void* p) {
    uint32_t a;
    asm("{ .reg .u64 t; cvta.to.shared.u64 t, %1; cvt.u32.u64 %0, t; }" : "=r"(a) : "l"(p));
    return a;
}

#define MBAR_INIT(a, c)  asm volatile("mbarrier.init.shared.b64 [%0], %1;" :: "r"((uint32_t)(a)), "r"((uint32_t)(c)) : "memory")
#define MBAR_ARRIVE(a)   asm volatile("mbarrier.arrive.shared.b64 _, [%0];" :: "r"((uint32_t)(a)) : "memory")

#define MBAR_WAIT(a, ph) do {                                                      \
    uint32_t _m = (uint32_t)(a), _p = (uint32_t)(ph);                              \
    asm volatile("{\n\t.reg .pred P;\n\t"                                          \
        "WL_%=:\n\t"                                                               \
        "mbarrier.try_wait.parity.acquire.cta.shared::cta.b64 P, [%0], %1, 0x989680;\n\t" \
        "@P bra.uni WD_%=;\n\t"                                                    \
        "bra.uni WL_%=;\n\t"                                                       \
        "WD_%=:\n\t}" :: "r"(_m), "r"(_p) : "memory");                             \
} while (0)

#define LDSM_X4(r, addr) \
    asm volatile("ldmatrix.sync.aligned.m8n8.x4.shared.b16 {%0,%1,%2,%3}, [%4];" \
        : "=r"((r)[0]), "=r"((r)[1]), "=r"((r)[2]), "=r"((r)[3]) : "r"((uint32_t)(addr)))

#define MMA16(d, a, b0, b1) \
    asm volatile("mma.sync.aligned.m16n8k16.row.col.f32.f16.f16.f32 " \
        "{%0,%1,%2,%3}, {%4,%5,%6,%7}, {%8,%9}, {%0,%1,%2,%3};" \
        : "+f"((d)[0]), "+f"((d)[1]), "+f"((d)[2]), "+f"((d)[3]) \
        : "r"((a)[0]), "r"((a)[1]), "r"((a)[2]), "r"((a)[3]), "r"(b0), "r"(b1))

// ---------------------------------------------------------------------------
__global__ void cov_fill(const float* __restrict__ mu, const float* __restrict__ logstd,
                         const float* __restrict__ eps, float* __restrict__ out) {
    int i = blockIdx.x * blockDim.x + threadIdx.x;
    if (i >= OUT_PLANE) return;
    int z = i & (ZDIM - 1);
    out[i] = mu[z];
    out[OUT_PLANE + i] = 2.0f * logstd[z];
    if (i < OUT_PLANE / 2) {
        int q  = i & 3;
        int l  = (i >> 2) & 31;
        int nP = (i >> 7) & 7;
        int kc = i >> 10;
        int n  = (2 * nP + (q >> 1)) * 8 + (l >> 2);
        int k  = kc * 16 + 2 * (l & 3) + 8 * (q & 1);
        g_epsh[i] = __floats2half2_rn(eps[(size_t)n * MDIM + k], eps[(size_t)n * MDIM + k + 1]);
    }
}

// ---------------------------------------------------------------------------
// 128 CTAs x 384 threads.
// warps 0-7: compute; warp = kpar(wid>>2) x mq((wid>>1)&1) x nh(wid&1); M32xN64.
// warps 8-11: producers — LDG fp32 B, convert fp16 (+fused sumsq), STS tile.
// eps B-fragments: direct LDG.128 from g_epsh (no smem), double-buffered.
// ---------------------------------------------------------------------------
__global__ void __launch_bounds__(384, 1) cov_main(
    const float* __restrict__ B, const float* __restrict__ mu,
    const float* __restrict__ logstd, float* __restrict__ out)
{
    extern __shared__ char smem_raw[];
    const uint32_t raw  = smem_u32(smem_raw);
    const uint32_t base = (raw + 1023u) & ~1023u;
    char* basep = smem_raw + (base - raw);
    float* ssp   = (float*)(basep + SS_OFF);
    float* smemC = (float*)basep;              // reused after main loop (32 KB)

    const int tid  = threadIdx.x;
    const int wid  = tid >> 5;
    const int lane = tid & 31;

    if (tid == 0) {
        #pragma unroll
        for (int s = 0; s < STAGES; s++) {
            MBAR_INIT(base + FULL_OFF  + s * 8, 128);  // 128 producer threads
            MBAR_INIT(base + EMPTY_OFF + s * 8, 4);    // lane0 of 4 consumer warps
        }
    }
    if (tid < MT) ssp[tid] = 0.0f;
    __syncthreads();

    float C[2][8][4];
    const int kpar = wid >> 2;
    const int mq   = (wid >> 1) & 1;
    const int nh   = wid & 1;
    const int g    = lane >> 2;
    const int tg   = lane & 3;

    if (wid < 8) {
        // ---------------- compute warps ----------------
        const uint32_t rowpat = (uint32_t)((lane & 7) + 8 * ((lane >> 3) & 1));
        const uint32_t swzl   = (uint32_t)(lane & 7) << 4;
        uint32_t aRow[2], colA[4];
        #pragma unroll
        for (int q = 0; q < 2; q++)
            aRow[q] = ((uint32_t)(mq * 32 + q * 16) + rowpat) * 128u;
        #pragma unroll
        for (int sk = 0; sk < 4; sk++)
            colA[sk] = ((uint32_t)(sk * 32 + 16 * (lane >> 4))) ^ swzl;

        #pragma unroll
        for (int q = 0; q < 2; q++)
            #pragma unroll
            for (int j = 0; j < 8; j++)
                #pragma unroll
                for (int e = 0; e < 4; e++) C[q][j][e] = 0.0f;

        const uint4* epsp = (const uint4*)g_epsh;
        uint4 bb0[4], bb1[4];
        // prefetch first k16-chunk (kc = first tile * 4)
        {
            int kc = kpar * 4;
            #pragma unroll
            for (int jp = 0; jp < 4; jp++)
                bb0[jp] = __ldg(&epsp[(size_t)((kc * 8 + nh * 4 + jp) * 32 + lane)]);
        }

        for (int ti = 0; ti < NITER / 2; ti++) {
            const int it = 2 * ti + kpar;
            const int s  = it & (STAGES - 1);
            const int ph = (it >> 3) & 1;
            MBAR_WAIT(base + FULL_OFF + s * 8, ph);
            const uint32_t stg = base + (uint32_t)s * AT_BYTES;

            #pragma unroll
            for (int sk = 0; sk < 4; sk++) {
                uint4* cur = (sk & 1) ? bb1 : bb0;
                uint4* nxt = (sk & 1) ? bb0 : bb1;
                const bool have_next = (sk < 3) || (ti < NITER / 2 - 1);
                const int kc_next = (sk < 3) ? (it * 4 + sk + 1) : ((it + 2) * 4);
                if (have_next) {
                    #pragma unroll
                    for (int jp = 0; jp < 4; jp++)
                        nxt[jp] = __ldg(&epsp[(size_t)((kc_next * 8 + nh * 4 + jp) * 32 + lane)]);
                }
                uint32_t a0[4], a1[4];
                LDSM_X4(a0, stg + aRow[0] + colA[sk]);
                LDSM_X4(a1, stg + aRow[1] + colA[sk]);
                #pragma unroll
                for (int jp = 0; jp < 4; jp++) {
                    MMA16(C[0][2 * jp    ], a0, cur[jp].x, cur[jp].y);
                    MMA16(C[1][2 * jp    ], a1, cur[jp].x, cur[jp].y);
                    MMA16(C[0][2 * jp + 1], a0, cur[jp].z, cur[jp].w);
                    MMA16(C[1][2 * jp + 1], a1, cur[jp].z, cur[jp].w);
                }
            }
            __syncwarp();
            if (lane == 0) MBAR_ARRIVE(base + EMPTY_OFF + s * 8);
        }
    } else {
        // ---------------- producer warps: convert B fp32->fp16 + sumsq ----------------
        const int pw = wid - 8;                   // 0..3
        const int lh = lane >> 4;                 // row parity within pair
        const int lc = lane & 15;                 // 16B chunk of the 256B fp32 row
        const float* gB = B + (size_t)blockIdx.x * MT * MDIM;

        float ss[8];
        #pragma unroll
        for (int i = 0; i < 8; i++) ss[i] = 0.0f;

        int s = 0, ph = 1;
        for (int it = 0; it < NITER; it++) {
            MBAR_WAIT(base + EMPTY_OFF + s * 8, ph);
            const uint32_t stg = base + (uint32_t)s * AT_BYTES;
            #pragma unroll
            for (int i = 0; i < 8; i++) {
                const int row = pw * 16 + 2 * i + lh;
                const float4 f = *(const float4*)(gB + (size_t)row * MDIM + it * KT + lc * 4);
                __half2 h0 = __floats2half2_rn(f.x, f.y);
                __half2 h1 = __floats2half2_rn(f.z, f.w);
                const uint32_t addr = stg + (uint32_t)row * 128u
                                    + (((uint32_t)(lc * 8)) ^ ((uint32_t)(row & 7) << 4));
                asm volatile("st.shared.v2.b32 [%0], {%1, %2};"
                             :: "r"(addr), "r"(*(uint32_t*)&h0), "r"(*(uint32_t*)&h1) : "memory");
                float c0 = __low2float(h0), c1 = __high2float(h0);
                float c2 = __low2float(h1), c3 = __high2float(h1);
                ss[i] = fmaf(c0, c0, ss[i]);
                ss[i] = fmaf(c1, c1, ss[i]);
                ss[i] = fmaf(c2, c2, ss[i]);
                ss[i] = fmaf(c3, c3, ss[i]);
            }
            MBAR_ARRIVE(base + FULL_OFF + s * 8);
            if (++s == STAGES) { s = 0; ph ^= 1; }
        }
        // reduce sumsq across the 16 k-chunk lanes of each row
        #pragma unroll
        for (int i = 0; i < 8; i++) {
            float v = ss[i];
            v += __shfl_xor_sync(0xffffffffu, v, 1);
            v += __shfl_xor_sync(0xffffffffu, v, 2);
            v += __shfl_xor_sync(0xffffffffu, v, 4);
            v += __shfl_xor_sync(0xffffffffu, v, 8);
            if (lc == 0) atomicAdd(&ssp[pw * 16 + 2 * i + lh], v);
        }
    }

    __syncthreads();                 // main-loop smem use done; ring reusable

    const int tg2 = 2 * tg;
    // kpar 0 warps store C into smemC[col*64 + row]
    if (wid < 4) {
        #pragma unroll
        for (int q = 0; q < 2; q++)
            #pragma unroll
            for (int j = 0; j < 8; j++) {
                int col = nh * 64 + j * 8 + tg2;
                int row = mq * 32 + q * 16 + g;
                smemC[(col    ) * 64 + row    ] = C[q][j][0];
                smemC[(col + 1) * 64 + row    ] = C[q][j][1];
                smemC[(col    ) * 64 + row + 8] = C[q][j][2];
                smemC[(col + 1) * 64 + row + 8] = C[q][j][3];
            }
    }
    __syncthreads();
    // kpar 1 warps accumulate
    if (wid >= 4 && wid < 8) {
        #pragma unroll
        for (int q = 0; q < 2; q++)
            #pragma unroll
            for (int j = 0; j < 8; j++) {
                int col = nh * 64 + j * 8 + tg2;
                int row = mq * 32 + q * 16 + g;
                smemC[(col    ) * 64 + row    ] += C[q][j][0];
                smemC[(col + 1) * 64 + row    ] += C[q][j][1];
                smemC[(col    ) * 64 + row + 8] += C[q][j][2];
                smemC[(col + 1) * 64 + row + 8] += C[q][j][3];
            }
    }
    __syncthreads();

    if (tid < 128) {
        int m = tid & 63, bh = tid >> 6;
        int mg = blockIdx.x * MT + m, z = mg & (ZDIM - 1);
        float sc  = rsqrtf(ssp[m]) * expf(logstd[z]);
        float muv = mu[z];
        float* op = out + 2 * (size_t)OUT_PLANE + mg;
        #pragma unroll 4
        for (int b = bh * 64; b < bh * 64 + 64; b++)
            op[(size_t)b * MDIM] = fmaf(sc, smemC[b * 64 + m], muv);
    }
}

extern "C" void kernel_launch(void* const* d_in, const int* in_sizes, int n_in,
                              void* d_out, int out_size) {
    const float* mu     = (const float*)d_in[0];
    const float* logstd = (const float*)d_in[1];
    const float* B      = (const float*)d_in[2];
    const float* eps    = (const float*)d_in[3];
    float* out = (float*)d_out;

    cudaFuncSetAttribute(cov_main, cudaFuncAttributeMaxDynamicSharedMemorySize, SMEM_DYN);

    cov_fill<<<(OUT_PLANE + 511) / 512, 512>>>(mu, logstd, eps, out);
    cov_main<<<NCTA, 384, SMEM_DYN>>>(B, mu, logstd, out);
}